// round 11
// baseline (speedup 1.0000x reference)
#include <cuda_runtime.h>
#include <stdint.h>

// MyDropout: out = x * mask; mask = JAX partitionable-threefry dropout
// (seed 42, p=0.1), columns < 64 zeroed. x: [16384, 4096] f32, N = 67108864.
//
//   bits(i) = o0 ^ o1, (o0,o1) = threefry2x32(key=(0,42), ctr=(0,i))
//   keep  <=>  bits < 0xE6666600
//
// alu pipe is the roofline: 20 rounds x {SHF, LOP3} = 40 alu-ops/elem
// (irreducible; SHF/LOP3 are alu-locked). Adds ride the fma pipe as IMAD via
// the opaque `one` parameter (round-9 win). This round: 8 elements/thread
// (2x float4) to amortize prologue/epilogue and deepen ILP to 8 hash chains.

#define TF_ROT(x, r) (((x) << (r)) | ((x) >> (32 - (r))))

// Add forced onto the fma pipe: IMAD Rd, Ra, one, Rb (`one` opaque to ptxas).
#define FADDU(a, b) ((a) * one + (b))

// One threefry round: add on fma pipe, SHF+LOP3 on alu pipe.
#define RND(r) do { x0 = FADDU(x0, x1); x1 = TF_ROT(x1, r) ^ x0; } while (0)

__device__ __forceinline__ uint32_t tf_bits(uint32_t i, uint32_t one) {
    const uint32_t k1 = 42u;
    const uint32_t k2 = 0x1BD11BF0u;   // 0x1BD11BDA ^ 0 ^ 42

    uint32_t x1 = FADDU(i, k1);        // ctr_lo + k1  (IMAD)
    uint32_t x0 = x1;                  // round-1 add: x0 = 0 + x1
    x1 = TF_ROT(x1, 13) ^ x0;          // rest of round 1
    RND(15); RND(26); RND(6);
    x0 = FADDU(x0, k1); x1 = FADDU(x1, k2 + 1u);
    RND(17); RND(29); RND(16); RND(24);
    x0 = FADDU(x0, k2); x1 = FADDU(x1, 2u);          // k0 = 0
    RND(13); RND(15); RND(26); RND(6);
    x1 = FADDU(x1, k1 + 3u);                          // x0 += k0 is a no-op
    RND(17); RND(29); RND(16); RND(24);
    x0 = FADDU(x0, k1); x1 = FADDU(x1, k2 + 4u);
    RND(13); RND(15); RND(26); RND(6);
    x0 = FADDU(x0, k2); x1 = FADDU(x1, 5u);          // k0 = 0
    return x0 ^ x1;                    // partitionable 32-bit output
}

__global__ __launch_bounds__(256) void mydropout_kernel(
    const float4* __restrict__ x, float4* __restrict__ out, uint32_t one) {
    const uint32_t KEEP_LT = 0xE6666600u;   // bits < this  <=>  keep (u < 0.9f)
    const float scale = (float)(1.0 / 0.9);

    uint32_t tid = blockIdx.x * blockDim.x + threadIdx.x;  // 8 elems / thread
    uint32_t v0 = tid * 2u;                                // first float4 index
    uint32_t g = v0 << 2;                                  // element index
    uint32_t col = g & 4095u;                              // column (row = 4096)

    if (col < 64u) {
        // K=64 leading columns zeroed; 8 | 64, so whole thread is zero.
        float4 z = make_float4(0.f, 0.f, 0.f, 0.f);
        out[v0] = z;
        out[v0 + 1u] = z;
        return;
    }

    float4 a = x[v0];
    float4 b = x[v0 + 1u];

    uint32_t h0 = tf_bits(g + 0u, one);
    uint32_t h1 = tf_bits(g + 1u, one);
    uint32_t h2 = tf_bits(g + 2u, one);
    uint32_t h3 = tf_bits(g + 3u, one);
    uint32_t h4 = tf_bits(g + 4u, one);
    uint32_t h5 = tf_bits(g + 5u, one);
    uint32_t h6 = tf_bits(g + 6u, one);
    uint32_t h7 = tf_bits(g + 7u, one);

    float4 ra, rb;
    ra.x = a.x * ((h0 < KEEP_LT) ? scale : 0.f);
    ra.y = a.y * ((h1 < KEEP_LT) ? scale : 0.f);
    ra.z = a.z * ((h2 < KEEP_LT) ? scale : 0.f);
    ra.w = a.w * ((h3 < KEEP_LT) ? scale : 0.f);
    rb.x = b.x * ((h4 < KEEP_LT) ? scale : 0.f);
    rb.y = b.y * ((h5 < KEEP_LT) ? scale : 0.f);
    rb.z = b.z * ((h6 < KEEP_LT) ? scale : 0.f);
    rb.w = b.w * ((h7 < KEEP_LT) ? scale : 0.f);

    out[v0] = ra;
    out[v0 + 1u] = rb;
}

extern "C" void kernel_launch(void* const* d_in, const int* in_sizes, int n_in,
                              void* d_out, int out_size) {
    const float4* x = (const float4*)d_in[0];
    float4* out = (float4*)d_out;
    const int threads = 256;
    const int blocks = 8388608 / threads;  // N/8 threads = 8,388,608 -> 32768
    mydropout_kernel<<<blocks, threads>>>(x, out, 1u /* opaque */);
}